// round 16
// baseline (speedup 1.0000x reference)
#include <cuda_runtime.h>
#include <cuda_fp16.h>
#include <cstdint>

// Problem constants
#define B_   2
#define T_   1024
#define CH_  1024
#define H_   16
#define KC_  64
#define WIN_ 4
#define MROWS (B_ * T_)          // 2048
#define BHT  (B_ * H_ * T_)     // 32768

#define LOG2E 1.4426950408889634f

// ---------------- scratch (static device globals; no allocation) ----------------
__device__ __half g_q[BHT * KC_];             // pre-scaled by log2e/sqrt(KC)
__device__ __half g_k[BHT * KC_];
__device__ __half g_v[BHT * KC_];
__device__ __half gx[MROWS * CH_];
__device__ __half gc[MROWS * CH_];
__device__ __half gw[4 * CH_ * CH_];          // W^T concat [q|k|v|o]
__device__ __half g_att[MROWS * CH_];
__device__ float g_bias[4 * CH_];
__device__ uint32_t g_mbits[MROWS * (T_ / 32)];

// ======================= helpers ================================================
// fp16-accumulator MMA: D (fp16x2 pair) = A*B + 0   (C = zero register pair)
__device__ __forceinline__ void mma_h16(uint32_t* d, const uint32_t* a,
                                        const uint32_t* b, uint32_t z)
{
    asm volatile(
        "mma.sync.aligned.m16n8k16.row.col.f16.f16.f16.f16 "
        "{%0,%1}, {%2,%3,%4,%5}, {%6,%7}, {%8,%8};"
        : "=r"(d[0]), "=r"(d[1])
        : "r"(a[0]), "r"(a[1]), "r"(a[2]), "r"(a[3]),
          "r"(b[0]), "r"(b[1]), "r"(z));
}

// unpack fp16x2 pair and add into fp32 accumulators (chunk promotion)
__device__ __forceinline__ void acc_h2(float* c, const uint32_t* d)
{
    __half2 p0 = *reinterpret_cast<const __half2*>(&d[0]);
    __half2 p1 = *reinterpret_cast<const __half2*>(&d[1]);
    c[0] += __low2float(p0);  c[1] += __high2float(p0);
    c[2] += __low2float(p1);  c[3] += __high2float(p1);
}

__device__ __forceinline__ void ldm_x4(uint32_t* r, uint32_t addr)
{
    asm volatile(
        "ldmatrix.sync.aligned.m8n8.x4.shared.b16 {%0,%1,%2,%3}, [%4];"
        : "=r"(r[0]), "=r"(r[1]), "=r"(r[2]), "=r"(r[3]) : "r"(addr));
}

__device__ __forceinline__ void ldm_x4_t(uint32_t* r, uint32_t addr)
{
    asm volatile(
        "ldmatrix.sync.aligned.m8n8.x4.trans.shared.b16 {%0,%1,%2,%3}, [%4];"
        : "=r"(r[0]), "=r"(r[1]), "=r"(r[2]), "=r"(r[3]) : "r"(addr));
}

__device__ __forceinline__ float ex2f(float x)
{
    float y;
    asm("ex2.approx.ftz.f32 %0, %1;" : "=f"(y) : "f"(x));
    return y;
}

__device__ __forceinline__ uint32_t pack_h2(float x, float y)
{
    __half2 t = __halves2half2(__float2half_rn(x), __float2half_rn(y));
    return *reinterpret_cast<uint32_t*>(&t);
}

__device__ __forceinline__ uint32_t smem_u32(const void* p) {
    uint32_t a;
    asm("{ .reg .u64 t; cvta.to.shared.u64 t, %1; cvt.u32.u64 %0, t; }"
        : "=r"(a) : "l"(p));
    return a;
}

__device__ __forceinline__ void cpa16(uint32_t dst, const void* src) {
    asm volatile("cp.async.cg.shared.global [%0], [%1], 16;" :: "r"(dst), "l"(src));
}

// ======================= merged prep kernel =====================================
__global__ __launch_bounds__(256) void prep(
    const float* __restrict__ x, const float* __restrict__ c,
    const int* __restrict__ mask,
    const float* __restrict__ Wq, const float* __restrict__ Wk,
    const float* __restrict__ Wv, const float* __restrict__ Wo,
    const float* __restrict__ bq, const float* __restrict__ bk,
    const float* __restrict__ bv, const float* __restrict__ bo)
{
    __shared__ float tile[32][33];
    int blk = blockIdx.x;
    int tid = threadIdx.x;

    if (blk < 4096) {
        int i = blk * 256 + tid;
        const float4* src;
        __half2* dst;
        int j;
        if (i < 524288) { src = (const float4*)x; j = i; dst = (__half2*)gx; }
        else            { src = (const float4*)c; j = i - 524288; dst = (__half2*)gc; }
        float4 v = src[j];
        dst[2 * j]     = __halves2half2(__float2half_rn(v.x), __float2half_rn(v.y));
        dst[2 * j + 1] = __halves2half2(__float2half_rn(v.z), __float2half_rn(v.w));
        if (i < 4096) {
            float b = (i < 1024) ? bq[i] : (i < 2048) ? bk[i - 1024]
                    : (i < 3072) ? bv[i - 2048] : bo[i - 3072];
            g_bias[i] = b;
        }
    } else if (blk < 8192) {
        int idx = blk - 4096;
        int z = idx >> 10, within = idx & 1023;
        int n0 = (within & 31) * 32, k0 = (within >> 5) * 32;
        const float* W = (z == 0) ? Wq : (z == 1) ? Wk : (z == 2) ? Wv : Wo;
        int tx = tid & 31, ty = tid >> 5;
#pragma unroll
        for (int u = 0; u < 4; ++u) {
            int k = k0 + ty + u * 8;
            tile[ty + u * 8][tx] = W[k * 1024 + n0 + tx];
        }
        __syncthreads();
#pragma unroll
        for (int u = 0; u < 4; ++u) {
            int r = ty + u * 8;
            gw[(z * 1024 + n0 + r) * 1024 + k0 + tx] = __float2half_rn(tile[tx][r]);
        }
    } else {
        int idx4 = (blk - 8192) * 256 + tid;
        int4 mv = ((const int4*)mask)[idx4];
        uint32_t v = (uint32_t)(mv.x != 0) | ((uint32_t)(mv.y != 0) << 1)
                   | ((uint32_t)(mv.z != 0) << 2) | ((uint32_t)(mv.w != 0) << 3);
        v |= __shfl_xor_sync(0xffffffffu, v, 1) << 4;
        v |= __shfl_xor_sync(0xffffffffu, v, 2) << 8;
        v |= __shfl_xor_sync(0xffffffffu, v, 4) << 16;
        if ((tid & 7) == 0) g_mbits[idx4 >> 3] = v;
    }
}

// ======================= fp16-acc 1-pass cp.async GEMM =========================
#define LDK 72
#define TILE_B (128 * LDK * 2)        // 18432 B
#define STAGE_B (2 * TILE_B)          // 36864 B
#define GEMM_SMEM (2 * STAGE_B)       // 73728 B
__global__ __launch_bounds__(256, 2) void gemm_mma(int mode, float* __restrict__ finalout)
{
    extern __shared__ __half sm[];
    uint32_t sbase = smem_u32(sm);

    int tid = threadIdx.x;
    int wid = tid >> 5, lane = tid & 31;
    int g = lane >> 2, tg = lane & 3;
    int warp_m = wid & 1, warp_n = wid >> 1;
    int z = (mode == 0) ? (int)blockIdx.z : 3;

    const __half* A = (mode == 1) ? g_att : (z == 0) ? gx : gc;
    int arow0 = blockIdx.y * 128;
    int brow0 = z * 1024 + blockIdx.x * 128;

    auto issue_stage = [&](int stage, int k0) {
        const __half* srcs[2] = {A, gw};
        int rows0[2] = {arow0, brow0};
        uint32_t stoff = sbase + (uint32_t)stage * STAGE_B;
#pragma unroll
        for (int arr = 0; arr < 2; ++arr) {
#pragma unroll
            for (int u = 0; u < 4; ++u) {
                int lin = tid + u * 256;
                int r = lin >> 3, c8 = lin & 7;
                cpa16(stoff + (uint32_t)arr * TILE_B + r * 144 + c8 * 16,
                      srcs[arr] + (size_t)(rows0[arr] + r) * 1024 + k0 + c8 * 8);
            }
        }
        asm volatile("cp.async.commit_group;" ::: "memory");
    };

    float acc[4][4][4];
#pragma unroll
    for (int mi = 0; mi < 4; ++mi)
#pragma unroll
        for (int ni = 0; ni < 4; ++ni)
#pragma unroll
            for (int e = 0; e < 4; ++e) acc[mi][ni][e] = 0.f;

    uint32_t a_off = (uint32_t)((warp_m * 64 + (lane & 15)) * 144 + ((lane >> 4) << 4));
    uint32_t b_off = (uint32_t)((warp_n * 32 + (((lane >> 4) & 1) << 3) + (lane & 7)) * 144
                                + (((lane >> 3) & 1) << 4));
    uint32_t zr = 0;

    issue_stage(0, 0);

    for (int s = 0; s < 16; ++s) {
        asm volatile("cp.async.wait_group 0;" ::: "memory");
        __syncthreads();
        if (s + 1 < 16) issue_stage((s + 1) & 1, (s + 1) * 64);

        uint32_t stb = sbase + (uint32_t)(s & 1) * STAGE_B;
        uint32_t aAb = stb, bWb = stb + TILE_B;

#pragma unroll
        for (int kk = 0; kk < 4; ++kk) {
            uint32_t kb = (uint32_t)kk * 32;
            uint32_t av[4][4], bw[2][4];
#pragma unroll
            for (int mi = 0; mi < 4; ++mi)
                ldm_x4(av[mi], aAb + a_off + (uint32_t)mi * (16 * 144) + kb);
#pragma unroll
            for (int p = 0; p < 2; ++p)
                ldm_x4(bw[p], bWb + b_off + (uint32_t)p * (16 * 144) + kb);
#pragma unroll
            for (int mi = 0; mi < 4; ++mi)
#pragma unroll
                for (int ni = 0; ni < 4; ++ni) {
                    uint32_t d[2];
                    mma_h16(d, av[mi], &bw[ni >> 1][(ni & 1) * 2], zr);
                    acc_h2(acc[mi][ni], d);
                }
        }
    }

    float scale = (mode == 0 && z == 0) ? (0.125f * LOG2E) : 1.0f;
#pragma unroll
    for (int mi = 0; mi < 4; ++mi) {
#pragma unroll
        for (int ni = 0; ni < 4; ++ni) {
#pragma unroll
            for (int e = 0; e < 4; ++e) {
                int row = blockIdx.y * 128 + warp_m * 64 + mi * 16 + g + ((e >> 1) ? 8 : 0);
                int col = blockIdx.x * 128 + warp_n * 32 + ni * 8 + 2 * tg + (e & 1);
                float v = (acc[mi][ni][e] + g_bias[z * 1024 + col]) * scale;
                if (mode == 0) {
                    int h = col >> 6, bb = row >> 10, t = row & 1023, d = col & 63;
                    int idx = (((bb * 16 + h) << 16) | (t << 6)) + d;
                    __half* dstg = (z == 0) ? g_q : (z == 1) ? g_k : g_v;
                    dstg[idx] = __float2half_rn(v);
                } else {
                    finalout[(size_t)row * 1024 + col] = v;
                }
            }
        }
    }
}

// =================== fused flash attention =======================================
// grid (16, 32), 128 threads (4 warps x 16 rows), 4 CTAs/SM. i-tile=64, j-tile=64.
#define ATT_SMEM 56064
#define MASKVAL (1e-4f * LOG2E)
__global__ __launch_bounds__(128, 4) void attn_fused(
    const float* __restrict__ erv, const float* __restrict__ erk)
{
    extern __shared__ char smc[];
    __half (*QS)[72] = (__half(*)[72])(smc);
    float (*BAND)[12] = (float(*)[12])(smc + 46080);
    float (*RLS)[9]   = (float(*)[9])(smc + 49152);
    float* ERVS       = (float*)(smc + 51456);
    float* ERKS       = (float*)(smc + 53760);

    uint32_t sb = smem_u32(smc);
    const uint32_t QS_a = sb;

    int tid = threadIdx.x, wid = tid >> 5, lane = tid & 31;
    int g = lane >> 2, tq = lane & 3;
    int bh = blockIdx.y, b = bh >> 4, h = bh & 15;
    int i0 = blockIdx.x * 64;

    uint32_t q_off = (uint32_t)((wid * 16 + (lane & 15)) * 144 + ((lane >> 4) << 4));
    uint32_t k_off = (uint32_t)(((((lane >> 4) & 1) << 3) + (lane & 7)) * 144
                                + (((lane >> 3) & 1) << 4));
    uint32_t v_off = (uint32_t)((lane & 15) * 144 + ((lane >> 4) << 4));
    uint32_t zr = 0;

    auto issue_kv = [&](int st, int j0) {
        uint32_t kb_ = sb + 9216 + (uint32_t)st * 9216;
        uint32_t vb_ = sb + 27648 + (uint32_t)st * 9216;
#pragma unroll
        for (int u = 0; u < 4; ++u) {
            int lin = tid + u * 128;
            int r = lin >> 3, c8 = lin & 7;
            const size_t go = (size_t)(bh * 1024 + j0 + r) * 64 + c8 * 8;
            cpa16(kb_ + r * 144 + c8 * 16, g_k + go);
            cpa16(vb_ + r * 144 + c8 * 16, g_v + go);
        }
        asm volatile("cp.async.commit_group;" ::: "memory");
    };

    // ---- load Q tile (64 rows), ERKS/ERVS, zero BAND; prefetch K/V tile 0 ----
#pragma unroll
    for (int u = 0; u < 4; ++u) {
        int lin = tid + u * 128;
        int r = lin >> 3, c8 = lin & 7;
        *(uint4*)&QS[r][c8 * 8] =
            *(const uint4*)(g_q + (size_t)(bh * 1024 + i0 + r) * 64 + c8 * 8);
    }
    for (int idx = tid; idx < 576; idx += 128) { ERVS[idx] = erv[idx]; ERKS[idx] = erk[idx]; }
    for (int idx = tid; idx < 64 * 12; idx += 128) ((float*)BAND)[idx] = 0.f;
    issue_kv(0, 0);
    __syncthreads();

    // ---- rel-k logits from resident Q tile (Q carries log2e scale) ----
    for (int idx = tid; idx < 576; idx += 128) {
        int r = idx / 9, u = idx - r * 9;
        float s = 0.f;
        const float* e = ERKS + u * 64;
#pragma unroll
        for (int d = 0; d < 64; ++d)
            s += __half2float(QS[r][d]) * e[d];
        RLS[r][u] = s;
    }

    float O[8][4];
#pragma unroll
    for (int nd = 0; nd < 8; ++nd)
#pragma unroll
        for (int e = 0; e < 4; ++e) O[nd][e] = 0.f;
    float m0 = -1e30f, m1 = -1e30f, l0 = 0.f, l1 = 0.f;

    const int rbase = wid * 16 + g;
    const uint32_t* mrow0 = g_mbits + ((size_t)(b << 10) + i0 + rbase) * 32;
    const uint32_t* mrow1 = mrow0 + 8 * 32;
    bool bstart = false;

    for (int jt = 0; jt < 16; ++jt) {
        int j0 = jt * 64;
        asm volatile("cp.async.wait_group 0;" ::: "memory");
        __syncthreads();
        if (jt + 1 < 16) issue_kv((jt + 1) & 1, (jt + 1) * 64);

        uint32_t KS_a = sb + 9216 + (uint32_t)(jt & 1) * 9216;
        uint32_t VS_a = sb + 27648 + (uint32_t)(jt & 1) * 9216;

        bool bp = (j0 + 67 >= i0 + rbase) && (j0 <= i0 + rbase + 12);

        // ---- S = Qs K^T (fp16-acc per-chunk, promote to fp32) ----
        float S[8][4];
#pragma unroll
        for (int nf = 0; nf < 8; ++nf)
#pragma unroll
            for (int e = 0; e < 4; ++e) S[nf][e] = 0.f;
#pragma unroll
        for (int ks = 0; ks < 4; ++ks) {
            uint32_t kb = (uint32_t)ks * 32;
            uint32_t aq[4];
            ldm_x4(aq, QS_a + q_off + kb);
#pragma unroll
            for (int p = 0; p < 4; ++p) {
                uint32_t k4[4];
                ldm_x4(k4, KS_a + k_off + (uint32_t)p * (16 * 144) + kb);
                uint32_t d0[2], d1[2];
                mma_h16(d0, aq, k4, zr);
                mma_h16(d1, aq, k4 + 2, zr);
                acc_h2(S[2 * p], d0);
                acc_h2(S[2 * p + 1], d1);
            }
        }

        // ---- fixup: rel-k band (gated) + mask (fast path); row max ----
        uint32_t mw[2][2];
        mw[0][0] = mrow0[(j0 >> 5)];     mw[0][1] = mrow0[(j0 >> 5) + 1];
        mw[1][0] = mrow1[(j0 >> 5)];     mw[1][1] = mrow1[(j0 >> 5) + 1];
        bool allpass = (mw[0][0] & mw[0][1] & mw[1][0] & mw[1][1]) == 0xffffffffu;
        float mx0 = -1e30f, mx1 = -1e30f;
#pragma unroll
        for (int nf = 0; nf < 8; ++nf) {
#pragma unroll
            for (int e = 0; e < 4; ++e) {
                int jloc = nf * 8 + 2 * tq + (e & 1);
                float s = S[nf][e];
                if (bp) {
                    int rl_ = rbase + ((e >> 1) << 3);
                    int d = (j0 + jloc) - (i0 + rl_);
                    if ((unsigned)(d + 4) <= 8u) s += RLS[rl_][d + 4];
                }
                if (!allpass &&
                    ((mw[e >> 1][nf >> 2] >> (jloc & 31)) & 1u) == 0u) s = MASKVAL;
                S[nf][e] = s;
                if (e < 2) mx0 = fmaxf(mx0, s); else mx1 = fmaxf(mx1, s);
            }
        }
        mx0 = fmaxf(mx0, __shfl_xor_sync(0xffffffffu, mx0, 1));
        mx0 = fmaxf(mx0, __shfl_xor_sync(0xffffffffu, mx0, 2));
        mx1 = fmaxf(mx1, __shfl_xor_sync(0xffffffffu, mx1, 1));
        mx1 = fmaxf(mx1, __shfl_xor_sync(0xffffffffu, mx1, 2));
        float mn0 = fmaxf(m0, mx0), mn1 = fmaxf(m1, mx1);
        float a0 = ex2f(m0 - mn0), a1 = ex2f(m1 - mn1);
        m0 = mn0; m1 = mn1;

#pragma unroll
        for (int nd = 0; nd < 8; ++nd) {
            O[nd][0] *= a0; O[nd][1] *= a0; O[nd][2] *= a1; O[nd][3] *= a1;
        }
        if (bstart && tq == 0) {
#pragma unroll
            for (int u = 0; u < 9; ++u) {
                BAND[rbase][u] *= a0;
                BAND[rbase + 8][u] *= a1;
            }
        }
        bstart = bstart || bp;
        __syncwarp();

        // ---- p = 2^(s - m), row sums, band adds (gated) ----
        float s0 = 0.f, s1 = 0.f;
#pragma unroll
        for (int nf = 0; nf < 8; ++nf) {
#pragma unroll
            for (int e = 0; e < 4; ++e) {
                float p = ex2f(S[nf][e] - ((e < 2) ? mn0 : mn1));
                S[nf][e] = p;
                if (e < 2) s0 += p; else s1 += p;
                if (bp) {
                    int rl_ = rbase + ((e >> 1) << 3);
                    int d = (j0 + nf * 8 + 2 * tq + (e & 1)) - (i0 + rl_);
                    if ((unsigned)(d + 4) <= 8u) BAND[rl_][d + 4] += p;
                }
            }
        }
        s0 += __shfl_xor_sync(0xffffffffu, s0, 1);
        s0 += __shfl_xor_sync(0xffffffffu, s0, 2);
        s1 += __shfl_xor_sync(0xffffffffu, s1, 1);
        s1 += __shfl_xor_sync(0xffffffffu, s1, 2);
        l0 = l0 * a0 + s0;
        l1 = l1 * a1 + s1;

        // ---- O += P V (fp16-acc per-chunk, promote to fp32) ----
#pragma unroll
        for (int kj = 0; kj < 4; ++kj) {
            uint32_t aP[4];
            aP[0] = pack_h2(S[2 * kj][0],     S[2 * kj][1]);
            aP[1] = pack_h2(S[2 * kj][2],     S[2 * kj][3]);
            aP[2] = pack_h2(S[2 * kj + 1][0], S[2 * kj + 1][1]);
            aP[3] = pack_h2(S[2 * kj + 1][2], S[2 * kj + 1][3]);
            uint32_t kjb = (uint32_t)kj * (16 * 144);
#pragma unroll
            for (int p = 0; p < 4; ++p) {
                uint32_t v4[4];
                ldm_x4_t(v4, VS_a + v_off + kjb + (uint32_t)p * 32);
                uint32_t d0[2], d1[2];
                mma_h16(d0, aP, v4, zr);
                mma_h16(d1, aP, v4 + 2, zr);
                acc_h2(O[2 * p], d0);
                acc_h2(O[2 * p + 1], d1);
            }
        }
    }
    __syncwarp();

    // ---- epilogue: out = (O + band . erv) / l, write fp16 g_att ----
    float inv0 = 1.f / l0, inv1 = 1.f / l1;
#pragma unroll
    for (int e = 0; e < 4; ++e) {
        int rl_ = rbase + ((e >> 1) << 3);
        float bnd[9];
#pragma unroll
        for (int u = 0; u < 9; ++u) bnd[u] = BAND[rl_][u];
        float inv = (e < 2) ? inv0 : inv1;
        size_t rowbase = ((size_t)(b * 1024 + i0 + rl_)) * 1024 + h * 64;
#pragma unroll
        for (int nd = 0; nd < 8; ++nd) {
            int dcol = nd * 8 + 2 * tq + (e & 1);
            float val = O[nd][e];
#pragma unroll
            for (int u = 0; u < 9; ++u) val += bnd[u] * ERVS[u * 64 + dcol];
            g_att[rowbase + dcol] = __float2half_rn(val * inv);
        }
    }
}

// --------------------------------- launch --------------------------------------
extern "C" void kernel_launch(void* const* d_in, const int* in_sizes, int n_in,
                              void* d_out, int out_size)
{
    const float* x   = (const float*)d_in[0];
    const float* c   = (const float*)d_in[1];
    const int*   msk = (const int*)  d_in[2];
    const float* Wq  = (const float*)d_in[3];
    const float* bq  = (const float*)d_in[4];
    const float* Wk  = (const float*)d_in[5];
    const float* bk  = (const float*)d_in[6];
    const float* Wv  = (const float*)d_in[7];
    const float* bv  = (const float*)d_in[8];
    const float* Wo  = (const float*)d_in[9];
    const float* bo  = (const float*)d_in[10];
    const float* erk = (const float*)d_in[11];
    const float* erv = (const float*)d_in[12];
    float* out = (float*)d_out;

    cudaFuncSetAttribute(gemm_mma, cudaFuncAttributeMaxDynamicSharedMemorySize, GEMM_SMEM);
    cudaFuncSetAttribute(attn_fused, cudaFuncAttributeMaxDynamicSharedMemorySize, ATT_SMEM);

    prep<<<10240, 256>>>(x, c, msk, Wq, Wk, Wv, Wo, bq, bk, bv, bo);
    gemm_mma<<<dim3(8, 16, 3), 256, GEMM_SMEM>>>(0, nullptr);   // Q,K,V
    attn_fused<<<dim3(16, 32), 128, ATT_SMEM>>>(erv, erk);      // 16 i-tiles x 32 bh
    gemm_mma<<<dim3(8, 16, 1), 256, GEMM_SMEM>>>(1, out);       // @Wo + bo
}

// round 17
// speedup vs baseline: 1.2328x; 1.2328x over previous
#include <cuda_runtime.h>
#include <cuda_fp16.h>
#include <cstdint>

// Problem constants
#define B_   2
#define T_   1024
#define CH_  1024
#define H_   16
#define KC_  64
#define WIN_ 4
#define MROWS (B_ * T_)          // 2048
#define BHT  (B_ * H_ * T_)     // 32768

#define LOG2E 1.4426950408889634f

// ---------------- scratch (static device globals; no allocation) ----------------
__device__ __half g_q[BHT * KC_];             // pre-scaled by log2e/sqrt(KC)
__device__ __half g_k[BHT * KC_];
__device__ __half g_v[BHT * KC_];
__device__ __half gx[MROWS * CH_];
__device__ __half gc[MROWS * CH_];
__device__ __half gw[4 * CH_ * CH_];          // W^T concat [q|k|v|o]
__device__ __half g_att[MROWS * CH_];
__device__ float g_bias[4 * CH_];
__device__ uint32_t g_mbits[MROWS * (T_ / 32)];

// ======================= helpers ================================================
__device__ __forceinline__ void mma_f16(float* c, const uint32_t* a, const uint32_t* b)
{
    asm volatile(
        "mma.sync.aligned.m16n8k16.row.col.f32.f16.f16.f32 "
        "{%0,%1,%2,%3}, {%4,%5,%6,%7}, {%8,%9}, {%0,%1,%2,%3};"
        : "+f"(c[0]), "+f"(c[1]), "+f"(c[2]), "+f"(c[3])
        : "r"(a[0]), "r"(a[1]), "r"(a[2]), "r"(a[3]), "r"(b[0]), "r"(b[1]));
}

__device__ __forceinline__ void ldm_x4(uint32_t* r, uint32_t addr)
{
    asm volatile(
        "ldmatrix.sync.aligned.m8n8.x4.shared.b16 {%0,%1,%2,%3}, [%4];"
        : "=r"(r[0]), "=r"(r[1]), "=r"(r[2]), "=r"(r[3]) : "r"(addr));
}

__device__ __forceinline__ void ldm_x4_t(uint32_t* r, uint32_t addr)
{
    asm volatile(
        "ldmatrix.sync.aligned.m8n8.x4.trans.shared.b16 {%0,%1,%2,%3}, [%4];"
        : "=r"(r[0]), "=r"(r[1]), "=r"(r[2]), "=r"(r[3]) : "r"(addr));
}

__device__ __forceinline__ float ex2f(float x)
{
    float y;
    asm("ex2.approx.ftz.f32 %0, %1;" : "=f"(y) : "f"(x));
    return y;
}

// pack two floats to f16x2 (lo=x, hi=y), then half2 EX2 -> packed p
__device__ __forceinline__ uint32_t ex2_h2(float x, float y)
{
    uint32_t t, r;
    asm("cvt.rn.f16x2.f32 %0, %2, %1;" : "=r"(t) : "f"(x), "f"(y));
    asm("ex2.approx.f16x2 %0, %1;" : "=r"(r) : "r"(t));
    return r;
}

__device__ __forceinline__ uint32_t smem_u32(const void* p) {
    uint32_t a;
    asm("{ .reg .u64 t; cvta.to.shared.u64 t, %1; cvt.u32.u64 %0, t; }"
        : "=r"(a) : "l"(p));
    return a;
}

__device__ __forceinline__ void cpa16(uint32_t dst, const void* src) {
    asm volatile("cp.async.cg.shared.global [%0], [%1], 16;" :: "r"(dst), "l"(src));
}

// ======================= merged prep kernel =====================================
__global__ __launch_bounds__(256) void prep(
    const float* __restrict__ x, const float* __restrict__ c,
    const int* __restrict__ mask,
    const float* __restrict__ Wq, const float* __restrict__ Wk,
    const float* __restrict__ Wv, const float* __restrict__ Wo,
    const float* __restrict__ bq, const float* __restrict__ bk,
    const float* __restrict__ bv, const float* __restrict__ bo)
{
    __shared__ float tile[32][33];
    int blk = blockIdx.x;
    int tid = threadIdx.x;

    if (blk < 4096) {
        int i = blk * 256 + tid;
        const float4* src;
        __half2* dst;
        int j;
        if (i < 524288) { src = (const float4*)x; j = i; dst = (__half2*)gx; }
        else            { src = (const float4*)c; j = i - 524288; dst = (__half2*)gc; }
        float4 v = src[j];
        dst[2 * j]     = __halves2half2(__float2half_rn(v.x), __float2half_rn(v.y));
        dst[2 * j + 1] = __halves2half2(__float2half_rn(v.z), __float2half_rn(v.w));
        if (i < 4096) {
            float b = (i < 1024) ? bq[i] : (i < 2048) ? bk[i - 1024]
                    : (i < 3072) ? bv[i - 2048] : bo[i - 3072];
            g_bias[i] = b;
        }
    } else if (blk < 8192) {
        int idx = blk - 4096;
        int z = idx >> 10, within = idx & 1023;
        int n0 = (within & 31) * 32, k0 = (within >> 5) * 32;
        const float* W = (z == 0) ? Wq : (z == 1) ? Wk : (z == 2) ? Wv : Wo;
        int tx = tid & 31, ty = tid >> 5;
#pragma unroll
        for (int u = 0; u < 4; ++u) {
            int k = k0 + ty + u * 8;
            tile[ty + u * 8][tx] = W[k * 1024 + n0 + tx];
        }
        __syncthreads();
#pragma unroll
        for (int u = 0; u < 4; ++u) {
            int r = ty + u * 8;
            gw[(z * 1024 + n0 + r) * 1024 + k0 + tx] = __float2half_rn(tile[tx][r]);
        }
    } else {
        int idx4 = (blk - 8192) * 256 + tid;
        int4 mv = ((const int4*)mask)[idx4];
        uint32_t v = (uint32_t)(mv.x != 0) | ((uint32_t)(mv.y != 0) << 1)
                   | ((uint32_t)(mv.z != 0) << 2) | ((uint32_t)(mv.w != 0) << 3);
        v |= __shfl_xor_sync(0xffffffffu, v, 1) << 4;
        v |= __shfl_xor_sync(0xffffffffu, v, 2) << 8;
        v |= __shfl_xor_sync(0xffffffffu, v, 4) << 16;
        if ((tid & 7) == 0) g_mbits[idx4 >> 3] = v;
    }
}

// ======================= fp16 1-pass cp.async GEMM (f32 acc) ====================
#define LDK 72
#define TILE_B (128 * LDK * 2)        // 18432 B
#define STAGE_B (2 * TILE_B)          // 36864 B
#define GEMM_SMEM (2 * STAGE_B)       // 73728 B
__global__ __launch_bounds__(256, 2) void gemm_mma(int mode, float* __restrict__ finalout)
{
    extern __shared__ __half sm[];
    uint32_t sbase = smem_u32(sm);

    int tid = threadIdx.x;
    int wid = tid >> 5, lane = tid & 31;
    int g = lane >> 2, tg = lane & 3;
    int warp_m = wid & 1, warp_n = wid >> 1;
    int z = (mode == 0) ? (int)blockIdx.z : 3;

    const __half* A = (mode == 1) ? g_att : (z == 0) ? gx : gc;
    int arow0 = blockIdx.y * 128;
    int brow0 = z * 1024 + blockIdx.x * 128;

    auto issue_stage = [&](int stage, int k0) {
        const __half* srcs[2] = {A, gw};
        int rows0[2] = {arow0, brow0};
        uint32_t stoff = sbase + (uint32_t)stage * STAGE_B;
#pragma unroll
        for (int arr = 0; arr < 2; ++arr) {
#pragma unroll
            for (int u = 0; u < 4; ++u) {
                int lin = tid + u * 256;
                int r = lin >> 3, c8 = lin & 7;
                cpa16(stoff + (uint32_t)arr * TILE_B + r * 144 + c8 * 16,
                      srcs[arr] + (size_t)(rows0[arr] + r) * 1024 + k0 + c8 * 8);
            }
        }
        asm volatile("cp.async.commit_group;" ::: "memory");
    };

    float acc[4][4][4];
#pragma unroll
    for (int mi = 0; mi < 4; ++mi)
#pragma unroll
        for (int ni = 0; ni < 4; ++ni)
#pragma unroll
            for (int e = 0; e < 4; ++e) acc[mi][ni][e] = 0.f;

    uint32_t a_off = (uint32_t)((warp_m * 64 + (lane & 15)) * 144 + ((lane >> 4) << 4));
    uint32_t b_off = (uint32_t)((warp_n * 32 + (((lane >> 4) & 1) << 3) + (lane & 7)) * 144
                                + (((lane >> 3) & 1) << 4));

    issue_stage(0, 0);

    for (int s = 0; s < 16; ++s) {
        asm volatile("cp.async.wait_group 0;" ::: "memory");
        __syncthreads();
        if (s + 1 < 16) issue_stage((s + 1) & 1, (s + 1) * 64);

        uint32_t stb = sbase + (uint32_t)(s & 1) * STAGE_B;
        uint32_t aAb = stb, bWb = stb + TILE_B;

#pragma unroll
        for (int kk = 0; kk < 4; ++kk) {
            uint32_t kb = (uint32_t)kk * 32;
            uint32_t av[4][4], bw[2][4];
#pragma unroll
            for (int mi = 0; mi < 4; ++mi)
                ldm_x4(av[mi], aAb + a_off + (uint32_t)mi * (16 * 144) + kb);
#pragma unroll
            for (int p = 0; p < 2; ++p)
                ldm_x4(bw[p], bWb + b_off + (uint32_t)p * (16 * 144) + kb);
#pragma unroll
            for (int mi = 0; mi < 4; ++mi)
#pragma unroll
                for (int ni = 0; ni < 4; ++ni)
                    mma_f16(acc[mi][ni], av[mi], &bw[ni >> 1][(ni & 1) * 2]);
        }
    }

    float scale = (mode == 0 && z == 0) ? (0.125f * LOG2E) : 1.0f;
#pragma unroll
    for (int mi = 0; mi < 4; ++mi) {
#pragma unroll
        for (int ni = 0; ni < 4; ++ni) {
#pragma unroll
            for (int e = 0; e < 4; ++e) {
                int row = blockIdx.y * 128 + warp_m * 64 + mi * 16 + g + ((e >> 1) ? 8 : 0);
                int col = blockIdx.x * 128 + warp_n * 32 + ni * 8 + 2 * tg + (e & 1);
                float v = (acc[mi][ni][e] + g_bias[z * 1024 + col]) * scale;
                if (mode == 0) {
                    int h = col >> 6, bb = row >> 10, t = row & 1023, d = col & 63;
                    int idx = (((bb * 16 + h) << 16) | (t << 6)) + d;
                    __half* dstg = (z == 0) ? g_q : (z == 1) ? g_k : g_v;
                    dstg[idx] = __float2half_rn(v);
                } else {
                    finalout[(size_t)row * 1024 + col] = v;
                }
            }
        }
    }
}

// =================== fused flash attention =======================================
// grid (16, 32), 128 threads (4 warps x 16 rows), 4 CTAs/SM. i-tile=64, j-tile=64.
#define ATT_SMEM 56064
#define MASKVAL (1e-4f * LOG2E)
__global__ __launch_bounds__(128, 4) void attn_fused(
    const float* __restrict__ erv, const float* __restrict__ erk)
{
    extern __shared__ char smc[];
    __half (*QS)[72] = (__half(*)[72])(smc);
    float (*BAND)[12] = (float(*)[12])(smc + 46080);
    float (*RLS)[9]   = (float(*)[9])(smc + 49152);
    float* ERVS       = (float*)(smc + 51456);
    float* ERKS       = (float*)(smc + 53760);

    uint32_t sb = smem_u32(smc);
    const uint32_t QS_a = sb;

    int tid = threadIdx.x, wid = tid >> 5, lane = tid & 31;
    int g = lane >> 2, tq = lane & 3;
    int bh = blockIdx.y, b = bh >> 4, h = bh & 15;
    int i0 = blockIdx.x * 64;

    uint32_t q_off = (uint32_t)((wid * 16 + (lane & 15)) * 144 + ((lane >> 4) << 4));
    uint32_t k_off = (uint32_t)(((((lane >> 4) & 1) << 3) + (lane & 7)) * 144
                                + (((lane >> 3) & 1) << 4));
    uint32_t v_off = (uint32_t)((lane & 15) * 144 + ((lane >> 4) << 4));

    auto issue_kv = [&](int st, int j0) {
        uint32_t kb_ = sb + 9216 + (uint32_t)st * 9216;
        uint32_t vb_ = sb + 27648 + (uint32_t)st * 9216;
#pragma unroll
        for (int u = 0; u < 4; ++u) {
            int lin = tid + u * 128;
            int r = lin >> 3, c8 = lin & 7;
            const size_t go = (size_t)(bh * 1024 + j0 + r) * 64 + c8 * 8;
            cpa16(kb_ + r * 144 + c8 * 16, g_k + go);
            cpa16(vb_ + r * 144 + c8 * 16, g_v + go);
        }
        asm volatile("cp.async.commit_group;" ::: "memory");
    };

    // ---- load Q tile (64 rows), ERKS/ERVS, zero BAND; prefetch K/V tile 0 ----
#pragma unroll
    for (int u = 0; u < 4; ++u) {
        int lin = tid + u * 128;
        int r = lin >> 3, c8 = lin & 7;
        *(uint4*)&QS[r][c8 * 8] =
            *(const uint4*)(g_q + (size_t)(bh * 1024 + i0 + r) * 64 + c8 * 8);
    }
    for (int idx = tid; idx < 576; idx += 128) { ERVS[idx] = erv[idx]; ERKS[idx] = erk[idx]; }
    for (int idx = tid; idx < 64 * 12; idx += 128) ((float*)BAND)[idx] = 0.f;
    issue_kv(0, 0);
    __syncthreads();

    // ---- rel-k logits from resident Q tile (Q carries log2e scale) ----
    for (int idx = tid; idx < 576; idx += 128) {
        int r = idx / 9, u = idx - r * 9;
        float s = 0.f;
        const float* e = ERKS + u * 64;
#pragma unroll
        for (int d = 0; d < 64; ++d)
            s += __half2float(QS[r][d]) * e[d];
        RLS[r][u] = s;
    }

    float O[8][4];
#pragma unroll
    for (int nd = 0; nd < 8; ++nd)
#pragma unroll
        for (int e = 0; e < 4; ++e) O[nd][e] = 0.f;
    float m0 = -1e30f, m1 = -1e30f, l0 = 0.f, l1 = 0.f;

    const int rbase = wid * 16 + g;
    const uint32_t* mrow0 = g_mbits + ((size_t)(b << 10) + i0 + rbase) * 32;
    const uint32_t* mrow1 = mrow0 + 8 * 32;
    bool bstart = false;

    for (int jt = 0; jt < 16; ++jt) {
        int j0 = jt * 64;
        asm volatile("cp.async.wait_group 0;" ::: "memory");
        __syncthreads();
        if (jt + 1 < 16) issue_kv((jt + 1) & 1, (jt + 1) * 64);

        uint32_t KS_a = sb + 9216 + (uint32_t)(jt & 1) * 9216;
        uint32_t VS_a = sb + 27648 + (uint32_t)(jt & 1) * 9216;

        bool bp = (j0 + 67 >= i0 + rbase) && (j0 <= i0 + rbase + 12);

        // ---- S = Qs K^T (1 pass, f32 acc) ----
        float S[8][4];
#pragma unroll
        for (int nf = 0; nf < 8; ++nf)
#pragma unroll
            for (int e = 0; e < 4; ++e) S[nf][e] = 0.f;
#pragma unroll
        for (int ks = 0; ks < 4; ++ks) {
            uint32_t kb = (uint32_t)ks * 32;
            uint32_t aq[4];
            ldm_x4(aq, QS_a + q_off + kb);
#pragma unroll
            for (int p = 0; p < 4; ++p) {
                uint32_t k4[4];
                ldm_x4(k4, KS_a + k_off + (uint32_t)p * (16 * 144) + kb);
                mma_f16(S[2 * p],     aq, k4);
                mma_f16(S[2 * p + 1], aq, k4 + 2);
            }
        }

        // ---- fixup: rel-k band (gated) + mask (fast path); row max ----
        uint32_t mw[2][2];
        mw[0][0] = mrow0[(j0 >> 5)];     mw[0][1] = mrow0[(j0 >> 5) + 1];
        mw[1][0] = mrow1[(j0 >> 5)];     mw[1][1] = mrow1[(j0 >> 5) + 1];
        bool allpass = (mw[0][0] & mw[0][1] & mw[1][0] & mw[1][1]) == 0xffffffffu;
        float mx0 = -1e30f, mx1 = -1e30f;
#pragma unroll
        for (int nf = 0; nf < 8; ++nf) {
#pragma unroll
            for (int e = 0; e < 4; ++e) {
                int jloc = nf * 8 + 2 * tq + (e & 1);
                float s = S[nf][e];
                if (bp) {
                    int rl_ = rbase + ((e >> 1) << 3);
                    int d = (j0 + jloc) - (i0 + rl_);
                    if ((unsigned)(d + 4) <= 8u) s += RLS[rl_][d + 4];
                }
                if (!allpass &&
                    ((mw[e >> 1][nf >> 2] >> (jloc & 31)) & 1u) == 0u) s = MASKVAL;
                S[nf][e] = s;
                if (e < 2) mx0 = fmaxf(mx0, s); else mx1 = fmaxf(mx1, s);
            }
        }
        mx0 = fmaxf(mx0, __shfl_xor_sync(0xffffffffu, mx0, 1));
        mx0 = fmaxf(mx0, __shfl_xor_sync(0xffffffffu, mx0, 2));
        mx1 = fmaxf(mx1, __shfl_xor_sync(0xffffffffu, mx1, 1));
        mx1 = fmaxf(mx1, __shfl_xor_sync(0xffffffffu, mx1, 2));
        float mn0 = fmaxf(m0, mx0), mn1 = fmaxf(m1, mx1);
        float a0 = ex2f(m0 - mn0), a1 = ex2f(m1 - mn1);
        m0 = mn0; m1 = mn1;

        // warp-uniform skip when running max unchanged (a0==a1==1 exactly)
        bool noresc = __all_sync(0xffffffffu, (a0 == 1.f) && (a1 == 1.f));
        if (!noresc) {
#pragma unroll
            for (int nd = 0; nd < 8; ++nd) {
                O[nd][0] *= a0; O[nd][1] *= a0; O[nd][2] *= a1; O[nd][3] *= a1;
            }
            if (bstart && tq == 0) {
#pragma unroll
                for (int u = 0; u < 9; ++u) {
                    BAND[rbase][u] *= a0;
                    BAND[rbase + 8][u] *= a1;
                }
            }
        }
        bstart = bstart || bp;
        __syncwarp();

        // ---- p = 2^(s - m) via f16x2 EX2; row sums from unpacked halves ----
        float s0 = 0.f, s1 = 0.f;
        uint32_t P2[8][2];
#pragma unroll
        for (int nf = 0; nf < 8; ++nf) {
            uint32_t pA = ex2_h2(S[nf][0] - mn0, S[nf][1] - mn0);
            uint32_t pB = ex2_h2(S[nf][2] - mn1, S[nf][3] - mn1);
            P2[nf][0] = pA; P2[nf][1] = pB;
            __half2 hA = *reinterpret_cast<__half2*>(&pA);
            __half2 hB = *reinterpret_cast<__half2*>(&pB);
            float p0 = __low2float(hA), p1 = __high2float(hA);
            float p2 = __low2float(hB), p3 = __high2float(hB);
            s0 += p0 + p1;
            s1 += p2 + p3;
            if (bp) {
                int rl0 = rbase, rl1 = rbase + 8;
                int jb = j0 + nf * 8 + 2 * tq;
                int d0 = jb - (i0 + rl0), d1 = jb - (i0 + rl1);
                if ((unsigned)(d0 + 4) <= 8u) BAND[rl0][d0 + 4] += p0;
                if ((unsigned)(d0 + 5) <= 8u) BAND[rl0][d0 + 5] += p1;
                if ((unsigned)(d1 + 4) <= 8u) BAND[rl1][d1 + 4] += p2;
                if ((unsigned)(d1 + 5) <= 8u) BAND[rl1][d1 + 5] += p3;
            }
        }
        s0 += __shfl_xor_sync(0xffffffffu, s0, 1);
        s0 += __shfl_xor_sync(0xffffffffu, s0, 2);
        s1 += __shfl_xor_sync(0xffffffffu, s1, 1);
        s1 += __shfl_xor_sync(0xffffffffu, s1, 2);
        l0 = l0 * a0 + s0;
        l1 = l1 * a1 + s1;

        // ---- O += P V (1 pass; P already packed fp16) ----
#pragma unroll
        for (int kj = 0; kj < 4; ++kj) {
            uint32_t aP[4];
            aP[0] = P2[2 * kj][0];
            aP[1] = P2[2 * kj][1];
            aP[2] = P2[2 * kj + 1][0];
            aP[3] = P2[2 * kj + 1][1];
            uint32_t kjb = (uint32_t)kj * (16 * 144);
#pragma unroll
            for (int p = 0; p < 4; ++p) {
                uint32_t v4[4];
                ldm_x4_t(v4, VS_a + v_off + kjb + (uint32_t)p * 32);
                mma_f16(O[2 * p],     aP, v4);
                mma_f16(O[2 * p + 1], aP, v4 + 2);
            }
        }
    }
    __syncwarp();

    // ---- epilogue: out = (O + band . erv) / l, write fp16 g_att ----
    float inv0 = 1.f / l0, inv1 = 1.f / l1;
#pragma unroll
    for (int e = 0; e < 4; ++e) {
        int rl_ = rbase + ((e >> 1) << 3);
        float bnd[9];
#pragma unroll
        for (int u = 0; u < 9; ++u) bnd[u] = BAND[rl_][u];
        float inv = (e < 2) ? inv0 : inv1;
        size_t rowbase = ((size_t)(b * 1024 + i0 + rl_)) * 1024 + h * 64;
#pragma unroll
        for (int nd = 0; nd < 8; ++nd) {
            int dcol = nd * 8 + 2 * tq + (e & 1);
            float val = O[nd][e];
#pragma unroll
            for (int u = 0; u < 9; ++u) val += bnd[u] * ERVS[u * 64 + dcol];
            g_att[rowbase + dcol] = __float2half_rn(val * inv);
        }
    }
}

// --------------------------------- launch --------------------------------------
extern "C" void kernel_launch(void* const* d_in, const int* in_sizes, int n_in,
                              void* d_out, int out_size)
{
    const float* x   = (const float*)d_in[0];
    const float* c   = (const float*)d_in[1];
    const int*   msk = (const int*)  d_in[2];
    const float* Wq  = (const float*)d_in[3];
    const float* bq  = (const float*)d_in[4];
    const float* Wk  = (const float*)d_in[5];
    const float* bk  = (const float*)d_in[6];
    const float* Wv  = (const float*)d_in[7];
    const float* bv  = (const float*)d_in[8];
    const float* Wo  = (const float*)d_in[9];
    const float* bo  = (const float*)d_in[10];
    const float* erk = (const float*)d_in[11];
    const float* erv = (const float*)d_in[12];
    float* out = (float*)d_out;

    cudaFuncSetAttribute(gemm_mma, cudaFuncAttributeMaxDynamicSharedMemorySize, GEMM_SMEM);
    cudaFuncSetAttribute(attn_fused, cudaFuncAttributeMaxDynamicSharedMemorySize, ATT_SMEM);

    prep<<<10240, 256>>>(x, c, msk, Wq, Wk, Wv, Wo, bq, bk, bv, bo);
    gemm_mma<<<dim3(8, 16, 3), 256, GEMM_SMEM>>>(0, nullptr);   // Q,K,V
    attn_fused<<<dim3(16, 32), 128, ATT_SMEM>>>(erv, erk);      // 16 i-tiles x 32 bh
    gemm_mma<<<dim3(8, 16, 1), 256, GEMM_SMEM>>>(1, out);       // @Wo + bo
}